// round 4
// baseline (speedup 1.0000x reference)
#include <cuda_runtime.h>
#include <math.h>

// Problem constants
#define B_   8
#define S_   1024
#define D_   512
#define NH_  8
#define HD_  64
#define MT_  (B_ * S_)      // 8192 rows
#define BH_  (B_ * NH_)     // 64 batch*head

// -------- device scratch (allocation-free: static __device__ globals) --------
__device__ float g_qh[MT_ * D_];
__device__ float g_kh[MT_ * D_];
__device__ float g_vh[MT_ * D_];
__device__ float g_ph[MT_ * D_];
__device__ float g_ctx[MT_ * D_];
__device__ float g_pos[(size_t)BH_ * S_ * S_];   // 256 MB raw pos scores P
__device__ float g_udot[BH_ * S_];               // u . kh[b,n]
__device__ float g_vdot[BH_ * S_];               // v_bias . ph[b,n]
__device__ int   g_mask_mode;                    // 0=u8, 1=i32, 2=f32

// ---------------------------------------------------------------------------
// Mask dtype detector (bool not in harness dtype list; sniff deterministically)
// ---------------------------------------------------------------------------
__global__ void detect_mask_kernel(const void* __restrict__ mask) {
    if (threadIdx.x != 0 || blockIdx.x != 0) return;
    const float* f = (const float*)mask;
    const int*   ip = (const int*)mask;
    bool f32ok = true, has1 = false;
    for (int i = 0; i < 1024; i++) {
        float v = f[i];
        if (!(v == 0.0f || v == 1.0f)) { f32ok = false; break; }
        if (v == 1.0f) has1 = true;
    }
    if (f32ok && has1) { g_mask_mode = 2; return; }
    bool i32ok = true;
    for (int i = 0; i < 1024; i++) {
        int v = ip[i];
        if (v != 0 && v != 1) { i32ok = false; break; }
    }
    g_mask_mode = i32ok ? 1 : 0;
}

// ---------------------------------------------------------------------------
// tf32 helpers
// ---------------------------------------------------------------------------
__device__ __forceinline__ unsigned f2tf(float x) {
    unsigned u;
    asm("cvt.rna.tf32.f32 %0, %1;" : "=r"(u) : "f"(x));
    return u;
}

__device__ __forceinline__ void mma8(float* d, const unsigned* a, const unsigned* b) {
    asm volatile(
        "mma.sync.aligned.m16n8k8.row.col.f32.tf32.tf32.f32 "
        "{%0,%1,%2,%3},{%4,%5,%6,%7},{%8,%9},{%0,%1,%2,%3};"
        : "+f"(d[0]), "+f"(d[1]), "+f"(d[2]), "+f"(d[3])
        : "r"(a[0]), "r"(a[1]), "r"(a[2]), "r"(a[3]), "r"(b[0]), "r"(b[1]));
}

// ---------------------------------------------------------------------------
// Bias dot tables: g_udot[bh][n] = u[h].kh[b,n,:], g_vdot[bh][n] = vb[h].ph[b,n,:]
// ---------------------------------------------------------------------------
__global__ void __launch_bounds__(256)
biasdot_kernel(const float* __restrict__ u_bias, const float* __restrict__ v_bias)
{
    const int bh = blockIdx.x, b = bh >> 3, h = bh & 7;
    const int tid = threadIdx.x;
    #pragma unroll
    for (int i = 0; i < 4; i++) {
        const int n = tid + (i << 8);
        const float* kp = g_kh + (size_t)((b << 10) + n) * D_ + (h << 6);
        const float* pp = g_ph + (size_t)((b << 10) + n) * D_ + (h << 6);
        float su = 0.0f, sv = 0.0f;
        #pragma unroll 16
        for (int d = 0; d < 64; d++) {
            su += u_bias[(h << 6) + d] * kp[d];
            sv += v_bias[(h << 6) + d] * pp[d];
        }
        g_udot[(bh << 10) + n] = su;
        g_vdot[(bh << 10) + n] = sv;
    }
}

// ---------------------------------------------------------------------------
// NT tf32 GEMM (projections / out-proj): C[m,n] = sum_k A[m,k]*W[n,k] (+bias)
// Block tile 128x64, BK=32, 8 warps, warp tile 32x32. Prefetch next tile's
// global loads before compute so they overlap with the MMA work.
// ---------------------------------------------------------------------------
__global__ void __launch_bounds__(256)
gemm_nt_tf32(const float* __restrict__ A, const float* __restrict__ W,
             const float* __restrict__ bias, float* __restrict__ C)
{
    __shared__ unsigned As[128][36];
    __shared__ unsigned Bs[64][36];
    const int tid  = threadIdx.x;
    const int warp = tid >> 5, lane = tid & 31;
    const int g = lane >> 2, t = lane & 3;
    const int wm = (warp >> 1) << 5, wn = (warp & 1) << 5;
    const int m0 = blockIdx.y << 7, n0 = blockIdx.x << 6;

    const int ar = tid >> 1, ac = (tid & 1) << 4;
    const int br = tid >> 2, bc = (tid & 3) << 3;

    const float* Ap = A + (size_t)(m0 + ar) * D_ + ac;
    const float* Wp = W + (size_t)(n0 + br) * D_ + bc;

    float acc[2][4][4] = {};

    float4 a0 = *(const float4*)(Ap + 0);
    float4 a1 = *(const float4*)(Ap + 4);
    float4 a2 = *(const float4*)(Ap + 8);
    float4 a3 = *(const float4*)(Ap + 12);
    float4 b0 = *(const float4*)(Wp + 0);
    float4 b1 = *(const float4*)(Wp + 4);

    for (int k0 = 0; k0 < D_; k0 += 32) {
        __syncthreads();
        *(uint4*)&As[ar][ac + 0]  = make_uint4(f2tf(a0.x), f2tf(a0.y), f2tf(a0.z), f2tf(a0.w));
        *(uint4*)&As[ar][ac + 4]  = make_uint4(f2tf(a1.x), f2tf(a1.y), f2tf(a1.z), f2tf(a1.w));
        *(uint4*)&As[ar][ac + 8]  = make_uint4(f2tf(a2.x), f2tf(a2.y), f2tf(a2.z), f2tf(a2.w));
        *(uint4*)&As[ar][ac + 12] = make_uint4(f2tf(a3.x), f2tf(a3.y), f2tf(a3.z), f2tf(a3.w));
        *(uint4*)&Bs[br][bc + 0]  = make_uint4(f2tf(b0.x), f2tf(b0.y), f2tf(b0.z), f2tf(b0.w));
        *(uint4*)&Bs[br][bc + 4]  = make_uint4(f2tf(b1.x), f2tf(b1.y), f2tf(b1.z), f2tf(b1.w));
        __syncthreads();
        if (k0 + 32 < D_) {
            const float* Apn = Ap + k0 + 32;
            const float* Wpn = Wp + k0 + 32;
            a0 = *(const float4*)(Apn + 0);
            a1 = *(const float4*)(Apn + 4);
            a2 = *(const float4*)(Apn + 8);
            a3 = *(const float4*)(Apn + 12);
            b0 = *(const float4*)(Wpn + 0);
            b1 = *(const float4*)(Wpn + 4);
        }
        #pragma unroll
        for (int kk = 0; kk < 4; kk++) {
            const int k8 = kk << 3;
            unsigned af[2][4], bf[4][2];
            #pragma unroll
            for (int mt = 0; mt < 2; mt++) {
                const int r = wm + (mt << 4) + g;
                af[mt][0] = As[r][k8 + t];
                af[mt][1] = As[r + 8][k8 + t];
                af[mt][2] = As[r][k8 + t + 4];
                af[mt][3] = As[r + 8][k8 + t + 4];
            }
            #pragma unroll
            for (int nt = 0; nt < 4; nt++) {
                const int r = wn + (nt << 3) + g;
                bf[nt][0] = Bs[r][k8 + t];
                bf[nt][1] = Bs[r][k8 + t + 4];
            }
            #pragma unroll
            for (int mt = 0; mt < 2; mt++)
                #pragma unroll
                for (int nt = 0; nt < 4; nt++)
                    mma8(acc[mt][nt], af[mt], bf[nt]);
        }
    }

    #pragma unroll
    for (int mt = 0; mt < 2; mt++) {
        #pragma unroll
        for (int nt = 0; nt < 4; nt++) {
            const int row = m0 + wm + (mt << 4) + g;
            const int col = n0 + wn + (nt << 3) + (t << 1);
            float bv0 = bias ? bias[col] : 0.0f;
            float bv1 = bias ? bias[col + 1] : 0.0f;
            C[(size_t)row * D_ + col]           = acc[mt][nt][0] + bv0;
            C[(size_t)row * D_ + col + 1]       = acc[mt][nt][1] + bv1;
            C[(size_t)(row + 8) * D_ + col]     = acc[mt][nt][2] + bv0;
            C[(size_t)(row + 8) * D_ + col + 1] = acc[mt][nt][3] + bv1;
        }
    }
}

// ---------------------------------------------------------------------------
// score_both: per (bh, 128q x 64n tile) compute BOTH
//   Craw[q,n] = qh[q].kh[n] + udot[n]   -> attn buffer (raw content scores)
//   Praw[q,n] = qh[q].ph[n] + vdot[n]   -> g_pos
// K=64 staged entirely once; A-fragments shared by both accumulator chains.
// Dynamic SMEM: As[128][68] | Bk[64][68] | Bp[64][68]  (unsigned tf32) = 68KB
// ---------------------------------------------------------------------------
#define SB_AS  0
#define SB_BK  (128 * 68)
#define SB_BP  (SB_BK + 64 * 68)
#define SB_WORDS (SB_BP + 64 * 68)
#define SB_BYTES (SB_WORDS * 4)

__global__ void __launch_bounds__(256)
score_both(float* __restrict__ attnC)
{
    extern __shared__ unsigned sbm[];
    unsigned* As = sbm + SB_AS;
    unsigned* Bk = sbm + SB_BK;
    unsigned* Bp = sbm + SB_BP;

    const int bh = blockIdx.z, b = bh >> 3, h = bh & 7;
    const int m0 = blockIdx.y << 7, n0 = blockIdx.x << 6;
    const int tid  = threadIdx.x;
    const int warp = tid >> 5, lane = tid & 31;
    const int g = lane >> 2, t = lane & 3;
    const int wm = (warp >> 1) << 5, wn = (warp & 1) << 5;

    // stage A: qh rows m0..m0+127, all 64 dims
    for (int i = tid; i < 512; i += 256) {
        const int r = i >> 2, c = (i & 3) << 4;
        const float* p = g_qh + (size_t)((b << 10) + m0 + r) * D_ + (h << 6) + c;
        float4 x0 = *(const float4*)(p + 0);
        float4 x1 = *(const float4*)(p + 4);
        float4 x2 = *(const float4*)(p + 8);
        float4 x3 = *(const float4*)(p + 12);
        *(uint4*)&As[r * 68 + c + 0]  = make_uint4(f2tf(x0.x), f2tf(x0.y), f2tf(x0.z), f2tf(x0.w));
        *(uint4*)&As[r * 68 + c + 4]  = make_uint4(f2tf(x1.x), f2tf(x1.y), f2tf(x1.z), f2tf(x1.w));
        *(uint4*)&As[r * 68 + c + 8]  = make_uint4(f2tf(x2.x), f2tf(x2.y), f2tf(x2.z), f2tf(x2.w));
        *(uint4*)&As[r * 68 + c + 12] = make_uint4(f2tf(x3.x), f2tf(x3.y), f2tf(x3.z), f2tf(x3.w));
    }
    // stage B: kh and ph rows n0..n0+63
    for (int i = tid; i < 256; i += 256) {
        const int r = i >> 2, c = (i & 3) << 4;
        const size_t gofs = (size_t)((b << 10) + n0 + r) * D_ + (h << 6) + c;
        const float* kp = g_kh + gofs;
        const float* pp = g_ph + gofs;
        #pragma unroll
        for (int j = 0; j < 4; j++) {
            float4 kv = *(const float4*)(kp + (j << 2));
            float4 pv = *(const float4*)(pp + (j << 2));
            *(uint4*)&Bk[r * 68 + c + (j << 2)] = make_uint4(f2tf(kv.x), f2tf(kv.y), f2tf(kv.z), f2tf(kv.w));
            *(uint4*)&Bp[r * 68 + c + (j << 2)] = make_uint4(f2tf(pv.x), f2tf(pv.y), f2tf(pv.z), f2tf(pv.w));
        }
    }
    __syncthreads();

    float accC[2][4][4] = {}, accP[2][4][4] = {};
    #pragma unroll
    for (int kk = 0; kk < 8; kk++) {
        const int k8 = kk << 3;
        unsigned af[2][4];
        #pragma unroll
        for (int mt = 0; mt < 2; mt++) {
            const int r = wm + (mt << 4) + g;
            af[mt][0] = As[r * 68 + k8 + t];
            af[mt][1] = As[(r + 8) * 68 + k8 + t];
            af[mt][2] = As[r * 68 + k8 + t + 4];
            af[mt][3] = As[(r + 8) * 68 + k8 + t + 4];
        }
        #pragma unroll
        for (int nt = 0; nt < 4; nt++) {
            const int r = wn + (nt << 3) + g;
            unsigned bk[2], bp[2];
            bk[0] = Bk[r * 68 + k8 + t];
            bk[1] = Bk[r * 68 + k8 + t + 4];
            bp[0] = Bp[r * 68 + k8 + t];
            bp[1] = Bp[r * 68 + k8 + t + 4];
            #pragma unroll
            for (int mt = 0; mt < 2; mt++) {
                mma8(accC[mt][nt], af[mt], bk);
                mma8(accP[mt][nt], af[mt], bp);
            }
        }
    }

    float* Cout = attnC + ((size_t)bh << 20);
    float* Pout = g_pos + ((size_t)bh << 20);
    #pragma unroll
    for (int mt = 0; mt < 2; mt++)
        #pragma unroll
        for (int nt = 0; nt < 4; nt++) {
            const int row = m0 + wm + (mt << 4) + g;
            const int col = n0 + wn + (nt << 3) + (t << 1);
            const float ud0 = g_udot[(bh << 10) + col];
            const float ud1 = g_udot[(bh << 10) + col + 1];
            const float vd0 = g_vdot[(bh << 10) + col];
            const float vd1 = g_vdot[(bh << 10) + col + 1];
            Cout[((size_t)row << 10) + col]           = accC[mt][nt][0] + ud0;
            Cout[((size_t)row << 10) + col + 1]       = accC[mt][nt][1] + ud1;
            Cout[((size_t)(row + 8) << 10) + col]     = accC[mt][nt][2] + ud0;
            Cout[((size_t)(row + 8) << 10) + col + 1] = accC[mt][nt][3] + ud1;
            Pout[((size_t)row << 10) + col]           = accP[mt][nt][0] + vd0;
            Pout[((size_t)row << 10) + col + 1]       = accP[mt][nt][1] + vd1;
            Pout[((size_t)(row + 8) << 10) + col]     = accP[mt][nt][2] + vd0;
            Pout[((size_t)(row + 8) << 10) + col + 1] = accP[mt][nt][3] + vd1;
        }
}

// ---------------------------------------------------------------------------
// fused_sm_av: per (bh, 32-row q-strip)
//   read Craw rows + shifted P slices + mask -> scale -> row softmax
//   -> write attn (in place over Craw) AND keep normalized rows in SMEM
//   -> AV MMA: ctx[32,64] += attn_tile[32,1024] @ vh[1024,64]
// shift(q,k): k<=q -> P[q, k+(S-1-q)] ; k==q+1 -> 0 ; k>q+1 -> P[q+1, k-q-2]
// Dynamic SMEM: Sx[32][1028] float | Vs[64][68] tf32  = 149KB
// ---------------------------------------------------------------------------
#define FS_STRIDE 1028
#define FS_VS_OFF (32 * FS_STRIDE)
#define FS_WORDS  (FS_VS_OFF + 64 * 68)
#define FS_BYTES  (FS_WORDS * 4)

__global__ void __launch_bounds__(256)
fused_sm_av(const void* __restrict__ mask, float* __restrict__ attn)
{
    extern __shared__ float fsm[];
    float*    Sx = fsm;
    unsigned* Vs = (unsigned*)(fsm + FS_VS_OFF);

    const int bh = blockIdx.y, b = bh >> 3, h = bh & 7;
    const int q0 = blockIdx.x << 5;
    const int tid  = threadIdx.x;
    const int warp = tid >> 5, lane = tid & 31;
    const int g = lane >> 2, t = lane & 3;

    const float scale = 0.04419417382415922f;  // 1/sqrt(512)
    const int mm = g_mask_mode;

    // ---- softmax phase: warp w handles rows 4w .. 4w+3
    #pragma unroll
    for (int rr = 0; rr < 4; rr++) {
        const int r = (warp << 2) + rr;
        const int q = q0 + r;
        const int off1 = (S_ - 1) - q;
        float* Crow = attn + ((size_t)bh << 20) + ((size_t)q << 10);
        const float* P0 = g_pos + ((size_t)bh << 20) + ((size_t)q << 10);
        const float* P1 = P0 + 1024;
        const size_t midx0 = ((size_t)b << 20) + ((size_t)q << 10);

        float vals[32];
        float mx = -1e30f;
        #pragma unroll
        for (int c = 0; c < 32; c++) {
            const int k = (c << 5) + lane;
            float p;
            if (k <= q)          p = P0[k + off1];
            else if (k == q + 1) p = 0.0f;
            else                 p = P1[k - q - 2];
            float sc = (Crow[k] + p) * scale;
            bool msk;
            if (mm == 1)      msk = ((const int*)mask)[midx0 + k] != 0;
            else if (mm == 2) msk = ((const float*)mask)[midx0 + k] != 0.0f;
            else              msk = ((const unsigned char*)mask)[midx0 + k] != 0;
            vals[c] = msk ? -10000.0f : sc;
            mx = fmaxf(mx, vals[c]);
        }
        #pragma unroll
        for (int o = 16; o > 0; o >>= 1) mx = fmaxf(mx, __shfl_xor_sync(0xffffffffu, mx, o));
        float sum = 0.0f;
        #pragma unroll
        for (int c = 0; c < 32; c++) {
            vals[c] = __expf(vals[c] - mx);
            sum += vals[c];
        }
        #pragma unroll
        for (int o = 16; o > 0; o >>= 1) sum += __shfl_xor_sync(0xffffffffu, sum, o);
        const float inv = 1.0f / sum;
        #pragma unroll
        for (int c = 0; c < 32; c++) {
            const int k = (c << 5) + lane;
            const float a = vals[c] * inv;
            Crow[k] = a;
            Sx[r * FS_STRIDE + k] = a;
        }
    }

    // ---- AV phase: 8 warps as 2m x 4n, warp tile 16x16, K=1024 in 16 chunks
    const int warp_m = warp & 1, warp_n = warp >> 1;
    float acc[2][4] = {};

    for (int kc = 0; kc < 16; kc++) {
        const int k0 = kc << 6;
        __syncthreads();
        // stage Vs[64][64] tf32 from g_vh
        for (int i = tid; i < 1024; i += 256) {
            const int r = i >> 4, c = (i & 15) << 2;
            float4 vv = *(const float4*)&g_vh[(size_t)((b << 10) + k0 + r) * D_ + (h << 6) + c];
            *(uint4*)&Vs[r * 68 + c] = make_uint4(f2tf(vv.x), f2tf(vv.y), f2tf(vv.z), f2tf(vv.w));
        }
        __syncthreads();
        #pragma unroll
        for (int ks = 0; ks < 8; ks++) {
            const int k8 = ks << 3;
            const int rowA = (warp_m << 4) + g;
            unsigned af[4];
            af[0] = f2tf(Sx[rowA * FS_STRIDE + k0 + k8 + t]);
            af[1] = f2tf(Sx[(rowA + 8) * FS_STRIDE + k0 + k8 + t]);
            af[2] = f2tf(Sx[rowA * FS_STRIDE + k0 + k8 + t + 4]);
            af[3] = f2tf(Sx[(rowA + 8) * FS_STRIDE + k0 + k8 + t + 4]);
            #pragma unroll
            for (int nt = 0; nt < 2; nt++) {
                const int col = (warp_n << 4) + (nt << 3) + g;
                unsigned bf[2];
                bf[0] = Vs[(k8 + t) * 68 + col];
                bf[1] = Vs[(k8 + t + 4) * 68 + col];
                mma8(acc[nt], af, bf);
            }
        }
    }

    // ---- epilogue: ctx[32 x 64] per block
    #pragma unroll
    for (int nt = 0; nt < 2; nt++) {
        const int q   = q0 + (warp_m << 4) + g;
        const int col = (h << 6) + (warp_n << 4) + (nt << 3) + (t << 1);
        g_ctx[(size_t)((b << 10) + q) * D_ + col]         = acc[nt][0];
        g_ctx[(size_t)((b << 10) + q) * D_ + col + 1]     = acc[nt][1];
        g_ctx[(size_t)((b << 10) + q + 8) * D_ + col]     = acc[nt][2];
        g_ctx[(size_t)((b << 10) + q + 8) * D_ + col + 1] = acc[nt][3];
    }
}

// ---------------------------------------------------------------------------
// kernel_launch: graph-capturable pipeline, default stream, no allocations.
// Output layout: context [8,1024,512] then attn [8,8,1024,1024].
// ---------------------------------------------------------------------------
extern "C" void kernel_launch(void* const* d_in, const int* in_sizes, int n_in,
                              void* d_out, int out_size)
{
    const float* q    = (const float*)d_in[0];
    const float* k    = (const float*)d_in[1];
    const float* v    = (const float*)d_in[2];
    const float* pos  = (const float*)d_in[3];
    const void*  mask = d_in[4];
    const float* Wq   = (const float*)d_in[5];
    const float* bq   = (const float*)d_in[6];
    const float* Wk   = (const float*)d_in[7];
    const float* bk   = (const float*)d_in[8];
    const float* Wv   = (const float*)d_in[9];
    const float* bv   = (const float*)d_in[10];
    const float* Wpos = (const float*)d_in[11];
    const float* Wout = (const float*)d_in[12];
    const float* bout = (const float*)d_in[13];
    const float* u    = (const float*)d_in[14];
    const float* vb   = (const float*)d_in[15];

    float* out  = (float*)d_out;
    float* attn = out + (size_t)MT_ * D_;   // context first, then attn

    float *p_ctx;
    cudaGetSymbolAddress((void**)&p_ctx, g_ctx);
    float *p_qh, *p_kh, *p_vh, *p_ph;
    cudaGetSymbolAddress((void**)&p_qh,  g_qh);
    cudaGetSymbolAddress((void**)&p_kh,  g_kh);
    cudaGetSymbolAddress((void**)&p_vh,  g_vh);
    cudaGetSymbolAddress((void**)&p_ph,  g_ph);

    static bool attr_set = false;
    if (!attr_set) {
        cudaFuncSetAttribute(score_both,
                             cudaFuncAttributeMaxDynamicSharedMemorySize, SB_BYTES);
        cudaFuncSetAttribute(fused_sm_av,
                             cudaFuncAttributeMaxDynamicSharedMemorySize, FS_BYTES);
        attr_set = true;
    }

    detect_mask_kernel<<<1, 32>>>(mask);

    // Projections: x @ W^T + b  (tf32 tensor cores)
    dim3 gproj(D_ / 64, MT_ / 128);
    gemm_nt_tf32<<<gproj, 256>>>(q,   Wq,   bq,      p_qh);
    gemm_nt_tf32<<<gproj, 256>>>(k,   Wk,   bk,      p_kh);
    gemm_nt_tf32<<<gproj, 256>>>(v,   Wv,   bv,      p_vh);
    gemm_nt_tf32<<<gproj, 256>>>(pos, Wpos, nullptr, p_ph);

    // Bias dot tables (u.kh, vb.ph per (bh,n))
    biasdot_kernel<<<BH_, 256>>>(u, vb);

    // Both score GEMMs in one pass: Craw -> attn buffer, Praw -> g_pos
    dim3 gsb(S_ / 64, S_ / 128, BH_);
    score_both<<<gsb, 256, SB_BYTES>>>(attn);

    // Fused shift + mask + scale + softmax + attn write + AV
    dim3 gfs(S_ / 32, BH_);
    fused_sm_av<<<gfs, 256, FS_BYTES>>>(mask, attn);

    // Output projection: ctx @ Wout^T + bout -> d_out
    gemm_nt_tf32<<<gproj, 256>>>(p_ctx, Wout, bout, out);
}